// round 1
// baseline (speedup 1.0000x reference)
#include <cuda_runtime.h>
#include <math.h>

#define Tn  2048   // B*S tokens
#define Dm  1024
#define FFm 4096
#define Vv  32000
#define Bm  2
#define Sm  1024
#define Hm  16
#define Lm  6

// ---------------- scratch (static device globals; no allocation) ------------
__device__ float g_x  [Tn * Dm];
__device__ float g_h  [Tn * Dm];
__device__ float g_q  [Tn * Dm];
__device__ float g_k  [Tn * Dm];
__device__ float g_v  [Tn * Dm];
__device__ float g_att[Tn * Dm];
__device__ float g_gate[(long)Tn * FFm];
__device__ float g_up  [(long)Tn * FFm];

// ---------------- embedding + positional ------------------------------------
__global__ void embed_kernel(const int* __restrict__ ids,
                             const float* __restrict__ et,
                             const float* __restrict__ es,
                             const float* __restrict__ pe,
                             float* __restrict__ x) {
    int t  = blockIdx.x;
    int id = ids[t];
    int s  = t % Sm;
    for (int d = threadIdx.x; d < Dm; d += blockDim.x) {
        long wi = (long)id * Dm + d;
        x[(long)t * Dm + d] = et[wi] * es[wi >> 7] + pe[s * Dm + d];
    }
}

// ---------------- RMSNorm (one block per token) ------------------------------
__global__ void rms_kernel(const float* __restrict__ X,
                           const float* __restrict__ w,
                           float* __restrict__ Y) {
    int t = blockIdx.x, tid = threadIdx.x;
    __shared__ float red[256];
    float s = 0.f;
    for (int d = tid; d < Dm; d += 256) {
        float v = X[(long)t * Dm + d];
        s += v * v;
    }
    red[tid] = s; __syncthreads();
    for (int o = 128; o > 0; o >>= 1) {
        if (tid < o) red[tid] += red[tid + o];
        __syncthreads();
    }
    float r = rsqrtf(red[0] / Dm + 1e-6f);
    for (int d = tid; d < Dm; d += 256)
        Y[(long)t * Dm + d] = X[(long)t * Dm + d] * r * w[d];
}

// ---------------- tiled SGEMM with on-the-fly group dequant ------------------
// Y[t,r] = (res ? res[t,r] : 0) + sum_c X[t,c] * W[r,c] * Sc[(r*IN+c)/128]
// T,R multiples of 64; IN multiple of 16.
__global__ void gemm_dq_kernel(const float* __restrict__ X,
                               const float* __restrict__ W,
                               const float* __restrict__ Sc,
                               const float* __restrict__ res,
                               float* __restrict__ Y,
                               int T, int R, int IN) {
    const int BM = 64, BN = 64, BK = 16;
    __shared__ float sX[BK][BM + 1];
    __shared__ float sW[BK][BN + 1];
    int bm = blockIdx.y * BM, bn = blockIdx.x * BN;
    int tid = threadIdx.x;
    int tr = tid >> 4, tc = tid & 15;

    float acc[4][4] = {};
    for (int k0 = 0; k0 < IN; k0 += BK) {
        #pragma unroll
        for (int i = tid; i < BM * BK; i += 256) {
            int m = i >> 4, k = i & 15;
            sX[k][m] = X[(long)(bm + m) * IN + k0 + k];
        }
        #pragma unroll
        for (int i = tid; i < BN * BK; i += 256) {
            int n = i >> 4, k = i & 15;
            long wi = (long)(bn + n) * IN + k0 + k;
            sW[k][n] = W[wi] * Sc[wi >> 7];
        }
        __syncthreads();
        #pragma unroll
        for (int k = 0; k < BK; k++) {
            float xv[4], wv[4];
            #pragma unroll
            for (int i = 0; i < 4; i++) xv[i] = sX[k][tr * 4 + i];
            #pragma unroll
            for (int j = 0; j < 4; j++) wv[j] = sW[k][tc * 4 + j];
            #pragma unroll
            for (int i = 0; i < 4; i++)
                #pragma unroll
                for (int j = 0; j < 4; j++)
                    acc[i][j] = fmaf(xv[i], wv[j], acc[i][j]);
        }
        __syncthreads();
    }
    #pragma unroll
    for (int i = 0; i < 4; i++) {
        int t = bm + tr * 4 + i;
        #pragma unroll
        for (int j = 0; j < 4; j++) {
            int r = bn + tc * 4 + j;
            float v = acc[i][j];
            if (res) v += res[(long)t * R + r];
            Y[(long)t * R + r] = v;
        }
    }
}

// ---------------- causal attention, one block per (b,h,q) --------------------
// O[t, h*64+dh] = softmax(q·k/8)·V + alpha[l,h] * Hn[t, h*64+dh]
__global__ void attn_kernel(const float* __restrict__ Q,
                            const float* __restrict__ K,
                            const float* __restrict__ V,
                            const float* __restrict__ Hn,
                            const float* __restrict__ alpha,
                            int layer,
                            float* __restrict__ O) {
    int qi = blockIdx.x, h = blockIdx.y, b = blockIdx.z;
    int t = b * Sm + qi;
    int tid = threadIdx.x;
    __shared__ float sc[Sm];
    __shared__ float qv[64];
    __shared__ float red[128];

    if (tid < 64) qv[tid] = Q[(long)t * Dm + h * 64 + tid];
    __syncthreads();

    int nk = qi + 1;
    const float scale = 0.125f;  // 1/sqrt(64)
    float m = -1e30f;
    for (int j = tid; j < nk; j += 128) {
        const float* kp = &K[(long)(b * Sm + j) * Dm + h * 64];
        float s = 0.f;
        #pragma unroll
        for (int d = 0; d < 64; d++) s = fmaf(qv[d], kp[d], s);
        s *= scale;
        sc[j] = s;
        m = fmaxf(m, s);
    }
    red[tid] = m; __syncthreads();
    for (int o = 64; o > 0; o >>= 1) {
        if (tid < o) red[tid] = fmaxf(red[tid], red[tid + o]);
        __syncthreads();
    }
    m = red[0];
    __syncthreads();

    float sum = 0.f;
    for (int j = tid; j < nk; j += 128) {
        float e = expf(sc[j] - m);
        sc[j] = e;
        sum += e;
    }
    red[tid] = sum; __syncthreads();
    for (int o = 64; o > 0; o >>= 1) {
        if (tid < o) red[tid] += red[tid + o];
        __syncthreads();
    }
    float inv = 1.0f / red[0];

    if (tid < 64) {
        int dh = tid;
        float acc = 0.f;
        for (int j = 0; j < nk; j++)
            acc = fmaf(sc[j], V[(long)(b * Sm + j) * Dm + h * 64 + dh], acc);
        float a = alpha[layer * Hm + h];
        O[(long)t * Dm + h * 64 + dh] =
            acc * inv + a * Hn[(long)t * Dm + h * 64 + dh];
    }
}

// ---------------- SiLU(gate) * up, in-place into gate ------------------------
__global__ void silu_mul_kernel(float* __restrict__ g,
                                const float* __restrict__ u, long n) {
    long i = (long)blockIdx.x * blockDim.x + threadIdx.x;
    if (i < n) {
        float x = g[i];
        g[i] = (x / (1.f + expf(-x))) * u[i];
    }
}

// =============================================================================
extern "C" void kernel_launch(void* const* d_in, const int* in_sizes, int n_in,
                              void* d_out, int out_size) {
    const int*   ids    = (const int*)  d_in[0];
    const float* emb_t  = (const float*)d_in[1];
    const float* emb_s  = (const float*)d_in[2];
    const float* pos    = (const float*)d_in[3];
    const float* q_t    = (const float*)d_in[4];
    const float* q_s    = (const float*)d_in[5];
    const float* k_t    = (const float*)d_in[6];
    const float* k_s    = (const float*)d_in[7];
    const float* v_t    = (const float*)d_in[8];
    const float* v_s    = (const float*)d_in[9];
    const float* o_t    = (const float*)d_in[10];
    const float* o_s    = (const float*)d_in[11];
    const float* gt     = (const float*)d_in[12];
    const float* gs     = (const float*)d_in[13];
    const float* ut     = (const float*)d_in[14];
    const float* us     = (const float*)d_in[15];
    const float* dt     = (const float*)d_in[16];
    const float* ds     = (const float*)d_in[17];
    const float* alpha  = (const float*)d_in[18];
    const float* na_w   = (const float*)d_in[19];
    const float* nm_w   = (const float*)d_in[20];
    const float* nf_w   = (const float*)d_in[21];
    const float* head_t = (const float*)d_in[22];
    const float* head_s = (const float*)d_in[23];

    float *x, *h, *q, *k, *v, *att, *gate, *up;
    cudaGetSymbolAddress((void**)&x,    g_x);
    cudaGetSymbolAddress((void**)&h,    g_h);
    cudaGetSymbolAddress((void**)&q,    g_q);
    cudaGetSymbolAddress((void**)&k,    g_k);
    cudaGetSymbolAddress((void**)&v,    g_v);
    cudaGetSymbolAddress((void**)&att,  g_att);
    cudaGetSymbolAddress((void**)&gate, g_gate);
    cudaGetSymbolAddress((void**)&up,   g_up);

    const long sQ = (long)Dm * Dm / 128;   // 8192 scales / layer (q,k,v,o)
    const long sF = (long)Dm * FFm / 128;  // 32768 scales / layer (g,u,d)

    embed_kernel<<<Tn, 256>>>(ids, emb_t, emb_s, pos, x);

    dim3 gD(Dm / 64,  Tn / 64);   // 16 x 32
    dim3 gF(FFm / 64, Tn / 64);   // 64 x 32
    dim3 gV(Vv / 64,  Tn / 64);   // 500 x 32
    dim3 ga(Sm, Hm, Bm);

    for (int l = 0; l < Lm; l++) {
        rms_kernel<<<Tn, 256>>>(x, na_w + l * Dm, h);

        gemm_dq_kernel<<<gD, 256>>>(h, q_t + (long)l * Dm * Dm, q_s + l * sQ,
                                    nullptr, q, Tn, Dm, Dm);
        gemm_dq_kernel<<<gD, 256>>>(h, k_t + (long)l * Dm * Dm, k_s + l * sQ,
                                    nullptr, k, Tn, Dm, Dm);
        gemm_dq_kernel<<<gD, 256>>>(h, v_t + (long)l * Dm * Dm, v_s + l * sQ,
                                    nullptr, v, Tn, Dm, Dm);

        attn_kernel<<<ga, 128>>>(q, k, v, h, alpha, l, att);

        // x = x + att @ O^T   (fused residual; in-place safe: disjoint tiles)
        gemm_dq_kernel<<<gD, 256>>>(att, o_t + (long)l * Dm * Dm, o_s + l * sQ,
                                    x, x, Tn, Dm, Dm);

        rms_kernel<<<Tn, 256>>>(x, nm_w + l * Dm, h);

        gemm_dq_kernel<<<gF, 256>>>(h, gt + (long)l * FFm * Dm, gs + l * sF,
                                    nullptr, gate, Tn, FFm, Dm);
        gemm_dq_kernel<<<gF, 256>>>(h, ut + (long)l * FFm * Dm, us + l * sF,
                                    nullptr, up, Tn, FFm, Dm);

        long n = (long)Tn * FFm;
        silu_mul_kernel<<<(unsigned)((n + 255) / 256), 256>>>(gate, up, n);

        // x = x + (silu(gate)*up) @ D^T
        gemm_dq_kernel<<<gD, 256>>>(gate, dt + (long)l * Dm * FFm, ds + l * sF,
                                    x, x, Tn, Dm, FFm);
    }

    rms_kernel<<<Tn, 256>>>(x, nf_w, h);
    gemm_dq_kernel<<<gV, 256>>>(h, head_t, head_s, nullptr,
                                (float*)d_out, Tn, Vv, Dm);
}

// round 2
// speedup vs baseline: 1.8245x; 1.8245x over previous
#include <cuda_runtime.h>
#include <cuda_bf16.h>
#include <math.h>
#include <stdint.h>

#define Tn  2048   // B*S tokens
#define Dm  1024
#define FFm 4096
#define Vv  32000
#define Bm  2
#define Sm  1024
#define Hm  16
#define Lm  6

typedef __nv_bfloat16 bf16;

// ---------------- scratch (static device globals; no allocation) ------------
__device__ float g_x  [Tn * Dm];          // residual stream (fp32)
__device__ bf16  g_hh [Tn * Dm];          // rms output hi
__device__ bf16  g_hl [Tn * Dm];          // rms output lo
__device__ float g_q  [Tn * Dm];
__device__ float g_k  [Tn * Dm];
__device__ float g_v  [Tn * Dm];
__device__ bf16  g_ah [Tn * Dm];          // attn output hi
__device__ bf16  g_al [Tn * Dm];          // attn output lo
__device__ float g_gate[(long)Tn * FFm];
__device__ float g_up  [(long)Tn * FFm];
__device__ bf16  g_gh [(long)Tn * FFm];   // silu(gate)*up hi
__device__ bf16  g_gl [(long)Tn * FFm];   // silu(gate)*up lo

__device__ __forceinline__ void split_bf16(float v, bf16& hi, bf16& lo) {
    hi = __float2bfloat16(v);
    lo = __float2bfloat16(v - __bfloat162float(hi));
}

// ---------------- embedding + positional ------------------------------------
__global__ void embed_kernel(const int* __restrict__ ids,
                             const float* __restrict__ et,
                             const float* __restrict__ es,
                             const float* __restrict__ pe,
                             float* __restrict__ x) {
    int t  = blockIdx.x;
    int id = ids[t];
    int s  = t % Sm;
    for (int d = threadIdx.x; d < Dm; d += blockDim.x) {
        long wi = (long)id * Dm + d;
        x[(long)t * Dm + d] = et[wi] * es[wi >> 7] + pe[s * Dm + d];
    }
}

// ---------------- RMSNorm -> hi/lo bf16 --------------------------------------
__global__ void rms_kernel(const float* __restrict__ X,
                           const float* __restrict__ w,
                           bf16* __restrict__ Yh, bf16* __restrict__ Yl) {
    int t = blockIdx.x, tid = threadIdx.x;
    __shared__ float red[256];
    float s = 0.f;
    for (int d = tid; d < Dm; d += 256) {
        float v = X[(long)t * Dm + d];
        s += v * v;
    }
    red[tid] = s; __syncthreads();
    for (int o = 128; o > 0; o >>= 1) {
        if (tid < o) red[tid] += red[tid + o];
        __syncthreads();
    }
    float r = rsqrtf(red[0] / Dm + 1e-6f);
    for (int d = tid; d < Dm; d += 256) {
        float v = X[(long)t * Dm + d] * r * w[d];
        bf16 hi, lo; split_bf16(v, hi, lo);
        Yh[(long)t * Dm + d] = hi;
        Yl[(long)t * Dm + d] = lo;
    }
}

// ---------------- tensor-core GEMM with exact group dequant ------------------
// Y[t,r] = (res? res[t,r]:0) + sum_g Sc[r*(IN/128)+g] * sum_{c in g} x[t,c]*W[r,c]
// x = Xh + Xl (bf16 split), W ternary (exact in bf16), Sc fp32.
// Block tile 128x64, BK=64, 256 threads (8 warps, 32x32 warp tiles).
__global__ void gemm_mma_kernel(const bf16* __restrict__ Xh,
                                const bf16* __restrict__ Xl,
                                const float* __restrict__ W,
                                const float* __restrict__ Sc,
                                const float* __restrict__ res,
                                float* __restrict__ Y,
                                int T, int R, int IN) {
    __shared__ bf16 sAh[128][72];
    __shared__ bf16 sAl[128][72];
    __shared__ bf16 sB [64][72];

    const int tid  = threadIdx.x;
    const int warp = tid >> 5, lane = tid & 31;
    const int warpM = warp & 3, warpN = warp >> 2;
    const int bm = blockIdx.y * 128, bn = blockIdx.x * 64;
    const int groups = IN >> 7;

    const int lr = lane >> 2;          // 0..7
    const int lc = (lane & 3) << 1;    // 0,2,4,6

    float master[2][4][4];
    float temp  [2][4][4];
    #pragma unroll
    for (int a = 0; a < 2; a++)
        #pragma unroll
        for (int b = 0; b < 4; b++)
            #pragma unroll
            for (int c = 0; c < 4; c++) { master[a][b][c] = 0.f; temp[a][b][c] = 0.f; }

    for (int k0 = 0; k0 < IN; k0 += 64) {
        // ---- load A tiles (bf16 hi/lo), 128 rows x 64 cols, uint4 = 8 bf16
        {
            int row = tid >> 3;          // 0..31
            int c8  = (tid & 7) << 3;    // 0..56
            #pragma unroll
            for (int p = 0; p < 4; p++) {
                int m = row + p * 32;
                long gi = (long)(bm + m) * IN + k0 + c8;
                *(uint4*)&sAh[m][c8] = *(const uint4*)&Xh[gi];
                *(uint4*)&sAl[m][c8] = *(const uint4*)&Xl[gi];
            }
        }
        // ---- load W tile (fp32 ternary -> bf16 exact), 64 rows x 64 cols
        {
            int row = tid >> 4;          // 0..15
            int c4  = (tid & 15) << 2;   // 0..60
            #pragma unroll
            for (int p = 0; p < 4; p++) {
                int n = row + p * 16;
                float4 v = *(const float4*)&W[(long)(bn + n) * IN + k0 + c4];
                sB[n][c4 + 0] = __float2bfloat16(v.x);
                sB[n][c4 + 1] = __float2bfloat16(v.y);
                sB[n][c4 + 2] = __float2bfloat16(v.z);
                sB[n][c4 + 3] = __float2bfloat16(v.w);
            }
        }
        __syncthreads();

        #pragma unroll
        for (int ks = 0; ks < 4; ks++) {
            const int kb = ks * 16;
            uint32_t ah[2][4], al[2][4], bb[4][2];
            #pragma unroll
            for (int mt = 0; mt < 2; mt++) {
                int m0 = warpM * 32 + mt * 16;
                ah[mt][0] = *(const uint32_t*)&sAh[m0 + lr    ][kb + lc    ];
                ah[mt][1] = *(const uint32_t*)&sAh[m0 + lr + 8][kb + lc    ];
                ah[mt][2] = *(const uint32_t*)&sAh[m0 + lr    ][kb + lc + 8];
                ah[mt][3] = *(const uint32_t*)&sAh[m0 + lr + 8][kb + lc + 8];
                al[mt][0] = *(const uint32_t*)&sAl[m0 + lr    ][kb + lc    ];
                al[mt][1] = *(const uint32_t*)&sAl[m0 + lr + 8][kb + lc    ];
                al[mt][2] = *(const uint32_t*)&sAl[m0 + lr    ][kb + lc + 8];
                al[mt][3] = *(const uint32_t*)&sAl[m0 + lr + 8][kb + lc + 8];
            }
            #pragma unroll
            for (int nt = 0; nt < 4; nt++) {
                int n0 = warpN * 32 + nt * 8;
                bb[nt][0] = *(const uint32_t*)&sB[n0 + lr][kb + lc    ];
                bb[nt][1] = *(const uint32_t*)&sB[n0 + lr][kb + lc + 8];
            }
            #pragma unroll
            for (int mt = 0; mt < 2; mt++)
                #pragma unroll
                for (int nt = 0; nt < 4; nt++) {
                    float* d = temp[mt][nt];
                    asm volatile(
                        "mma.sync.aligned.m16n8k16.row.col.f32.bf16.bf16.f32 "
                        "{%0,%1,%2,%3}, {%4,%5,%6,%7}, {%8,%9}, {%0,%1,%2,%3};"
                        : "+f"(d[0]), "+f"(d[1]), "+f"(d[2]), "+f"(d[3])
                        : "r"(ah[mt][0]), "r"(ah[mt][1]), "r"(ah[mt][2]), "r"(ah[mt][3]),
                          "r"(bb[nt][0]), "r"(bb[nt][1]));
                    asm volatile(
                        "mma.sync.aligned.m16n8k16.row.col.f32.bf16.bf16.f32 "
                        "{%0,%1,%2,%3}, {%4,%5,%6,%7}, {%8,%9}, {%0,%1,%2,%3};"
                        : "+f"(d[0]), "+f"(d[1]), "+f"(d[2]), "+f"(d[3])
                        : "r"(al[mt][0]), "r"(al[mt][1]), "r"(al[mt][2]), "r"(al[mt][3]),
                          "r"(bb[nt][0]), "r"(bb[nt][1]));
                }
        }
        __syncthreads();

        // group boundary every 128 K: fold temp into master with fp32 scale
        if (((k0 + 64) & 127) == 0) {
            int g = k0 >> 7;
            #pragma unroll
            for (int nt = 0; nt < 4; nt++) {
                int r0 = bn + warpN * 32 + nt * 8 + lc;
                float s0 = __ldg(&Sc[(long)r0 * groups + g]);
                float s1 = __ldg(&Sc[(long)(r0 + 1) * groups + g]);
                #pragma unroll
                for (int mt = 0; mt < 2; mt++) {
                    master[mt][nt][0] += s0 * temp[mt][nt][0];
                    master[mt][nt][1] += s1 * temp[mt][nt][1];
                    master[mt][nt][2] += s0 * temp[mt][nt][2];
                    master[mt][nt][3] += s1 * temp[mt][nt][3];
                    temp[mt][nt][0] = 0.f; temp[mt][nt][1] = 0.f;
                    temp[mt][nt][2] = 0.f; temp[mt][nt][3] = 0.f;
                }
            }
        }
    }

    // ---- epilogue: optional residual, fp32 store (float2 per row pair)
    #pragma unroll
    for (int mt = 0; mt < 2; mt++) {
        int m0 = bm + warpM * 32 + mt * 16 + lr;
        #pragma unroll
        for (int nt = 0; nt < 4; nt++) {
            int r0 = bn + warpN * 32 + nt * 8 + lc;
            float2 v0 = make_float2(master[mt][nt][0], master[mt][nt][1]);
            float2 v1 = make_float2(master[mt][nt][2], master[mt][nt][3]);
            if (res) {
                float2 p0 = *(const float2*)&res[(long)m0 * R + r0];
                float2 p1 = *(const float2*)&res[(long)(m0 + 8) * R + r0];
                v0.x += p0.x; v0.y += p0.y;
                v1.x += p1.x; v1.y += p1.y;
            }
            *(float2*)&Y[(long)m0 * R + r0]       = v0;
            *(float2*)&Y[(long)(m0 + 8) * R + r0] = v1;
        }
    }
}

// ---------------- causal attention, one block per (b,h,q) --------------------
__global__ void attn_kernel(const float* __restrict__ Q,
                            const float* __restrict__ K,
                            const float* __restrict__ V,
                            const bf16* __restrict__ Hh,
                            const bf16* __restrict__ Hl,
                            const float* __restrict__ alpha,
                            int layer,
                            bf16* __restrict__ Oh, bf16* __restrict__ Ol) {
    int qi = blockIdx.x, h = blockIdx.y, b = blockIdx.z;
    int t = b * Sm + qi;
    int tid = threadIdx.x;
    __shared__ float sc[Sm];
    __shared__ float qv[64];
    __shared__ float red[128];

    if (tid < 64) qv[tid] = Q[(long)t * Dm + h * 64 + tid];
    __syncthreads();

    int nk = qi + 1;
    const float scale = 0.125f;
    float m = -1e30f;
    for (int j = tid; j < nk; j += 128) {
        const float* kp = &K[(long)(b * Sm + j) * Dm + h * 64];
        float s = 0.f;
        #pragma unroll
        for (int d = 0; d < 64; d++) s = fmaf(qv[d], kp[d], s);
        s *= scale;
        sc[j] = s;
        m = fmaxf(m, s);
    }
    red[tid] = m; __syncthreads();
    for (int o = 64; o > 0; o >>= 1) {
        if (tid < o) red[tid] = fmaxf(red[tid], red[tid + o]);
        __syncthreads();
    }
    m = red[0];
    __syncthreads();

    float sum = 0.f;
    for (int j = tid; j < nk; j += 128) {
        float e = expf(sc[j] - m);
        sc[j] = e;
        sum += e;
    }
    red[tid] = sum; __syncthreads();
    for (int o = 64; o > 0; o >>= 1) {
        if (tid < o) red[tid] += red[tid + o];
        __syncthreads();
    }
    float inv = 1.0f / red[0];

    if (tid < 64) {
        int dh = tid;
        float acc = 0.f;
        for (int j = 0; j < nk; j++)
            acc = fmaf(sc[j], V[(long)(b * Sm + j) * Dm + h * 64 + dh], acc);
        float a = alpha[layer * Hm + h];
        long oi = (long)t * Dm + h * 64 + dh;
        float hn = __bfloat162float(Hh[oi]) + __bfloat162float(Hl[oi]);
        float v = acc * inv + a * hn;
        bf16 hi, lo; split_bf16(v, hi, lo);
        Oh[oi] = hi; Ol[oi] = lo;
    }
}

// ---------------- SiLU(gate) * up -> hi/lo bf16 -------------------------------
__global__ void silu_mul_kernel(const float* __restrict__ g,
                                const float* __restrict__ u,
                                bf16* __restrict__ Yh, bf16* __restrict__ Yl,
                                long n) {
    long i = (long)blockIdx.x * blockDim.x + threadIdx.x;
    if (i < n) {
        float x = g[i];
        float v = (x / (1.f + expf(-x))) * u[i];
        bf16 hi, lo; split_bf16(v, hi, lo);
        Yh[i] = hi; Yl[i] = lo;
    }
}

// =============================================================================
extern "C" void kernel_launch(void* const* d_in, const int* in_sizes, int n_in,
                              void* d_out, int out_size) {
    const int*   ids    = (const int*)  d_in[0];
    const float* emb_t  = (const float*)d_in[1];
    const float* emb_s  = (const float*)d_in[2];
    const float* pos    = (const float*)d_in[3];
    const float* q_t    = (const float*)d_in[4];
    const float* q_s    = (const float*)d_in[5];
    const float* k_t    = (const float*)d_in[6];
    const float* k_s    = (const float*)d_in[7];
    const float* v_t    = (const float*)d_in[8];
    const float* v_s    = (const float*)d_in[9];
    const float* o_t    = (const float*)d_in[10];
    const float* o_s    = (const float*)d_in[11];
    const float* gt     = (const float*)d_in[12];
    const float* gs     = (const float*)d_in[13];
    const float* ut     = (const float*)d_in[14];
    const float* us     = (const float*)d_in[15];
    const float* dt     = (const float*)d_in[16];
    const float* ds     = (const float*)d_in[17];
    const float* alpha  = (const float*)d_in[18];
    const float* na_w   = (const float*)d_in[19];
    const float* nm_w   = (const float*)d_in[20];
    const float* nf_w   = (const float*)d_in[21];
    const float* head_t = (const float*)d_in[22];
    const float* head_s = (const float*)d_in[23];

    float *x, *q, *k, *v, *gate, *up;
    bf16 *hh, *hl, *ah, *al, *gh, *gl;
    cudaGetSymbolAddress((void**)&x,    g_x);
    cudaGetSymbolAddress((void**)&hh,   g_hh);
    cudaGetSymbolAddress((void**)&hl,   g_hl);
    cudaGetSymbolAddress((void**)&q,    g_q);
    cudaGetSymbolAddress((void**)&k,    g_k);
    cudaGetSymbolAddress((void**)&v,    g_v);
    cudaGetSymbolAddress((void**)&ah,   g_ah);
    cudaGetSymbolAddress((void**)&al,   g_al);
    cudaGetSymbolAddress((void**)&gate, g_gate);
    cudaGetSymbolAddress((void**)&up,   g_up);
    cudaGetSymbolAddress((void**)&gh,   g_gh);
    cudaGetSymbolAddress((void**)&gl,   g_gl);

    const long sQ = (long)Dm * Dm / 128;
    const long sF = (long)Dm * FFm / 128;

    embed_kernel<<<Tn, 256>>>(ids, emb_t, emb_s, pos, x);

    dim3 gD(Dm / 64,  Tn / 128);   // 16 x 16
    dim3 gF(FFm / 64, Tn / 128);   // 64 x 16
    dim3 gV(Vv / 64,  Tn / 128);   // 500 x 16
    dim3 ga(Sm, Hm, Bm);

    for (int l = 0; l < Lm; l++) {
        rms_kernel<<<Tn, 256>>>(x, na_w + l * Dm, hh, hl);

        gemm_mma_kernel<<<gD, 256>>>(hh, hl, q_t + (long)l * Dm * Dm, q_s + l * sQ,
                                     nullptr, q, Tn, Dm, Dm);
        gemm_mma_kernel<<<gD, 256>>>(hh, hl, k_t + (long)l * Dm * Dm, k_s + l * sQ,
                                     nullptr, k, Tn, Dm, Dm);
        gemm_mma_kernel<<<gD, 256>>>(hh, hl, v_t + (long)l * Dm * Dm, v_s + l * sQ,
                                     nullptr, v, Tn, Dm, Dm);

        attn_kernel<<<ga, 128>>>(q, k, v, hh, hl, alpha, l, ah, al);

        // x = x + att @ O^T
        gemm_mma_kernel<<<gD, 256>>>(ah, al, o_t + (long)l * Dm * Dm, o_s + l * sQ,
                                     x, x, Tn, Dm, Dm);

        rms_kernel<<<Tn, 256>>>(x, nm_w + l * Dm, hh, hl);

        gemm_mma_kernel<<<gF, 256>>>(hh, hl, gt + (long)l * FFm * Dm, gs + l * sF,
                                     nullptr, gate, Tn, FFm, Dm);
        gemm_mma_kernel<<<gF, 256>>>(hh, hl, ut + (long)l * FFm * Dm, us + l * sF,
                                     nullptr, up, Tn, FFm, Dm);

        long n = (long)Tn * FFm;
        silu_mul_kernel<<<(unsigned)((n + 255) / 256), 256>>>(gate, up, gh, gl, n);

        // x = x + (silu(gate)*up) @ D^T
        gemm_mma_kernel<<<gD, 256>>>(gh, gl, dt + (long)l * Dm * FFm, ds + l * sF,
                                     x, x, Tn, Dm, FFm);
    }

    rms_kernel<<<Tn, 256>>>(x, nf_w, hh, hl);
    gemm_mma_kernel<<<gV, 256>>>(hh, hl, head_t, head_s, nullptr,
                                 (float*)d_out, Tn, Vv, Dm);
}

// round 3
// speedup vs baseline: 7.9514x; 4.3580x over previous
#include <cuda_runtime.h>
#include <cuda_bf16.h>
#include <math.h>
#include <stdint.h>

#define Tn  2048   // B*S tokens
#define Dm  1024
#define FFm 4096
#define Vv  32000
#define Bm  2
#define Sm  1024
#define Hm  16
#define Lm  6

typedef __nv_bfloat16 bf16;

// ---------------- scratch (static device globals; no allocation) ------------
__device__ float g_x  [Tn * Dm];          // residual stream (fp32)
__device__ bf16  g_hh [Tn * Dm];          // rms output hi
__device__ bf16  g_hl [Tn * Dm];          // rms output lo
__device__ float g_q  [Tn * Dm];
__device__ float g_k  [Tn * Dm];
__device__ float g_v  [Tn * Dm];
__device__ bf16  g_ah [Tn * Dm];          // attn output hi
__device__ bf16  g_al [Tn * Dm];          // attn output lo
__device__ float g_gate[(long)Tn * FFm];
__device__ float g_up  [(long)Tn * FFm];
__device__ bf16  g_gh [(long)Tn * FFm];   // silu(gate)*up hi
__device__ bf16  g_gl [(long)Tn * FFm];   // silu(gate)*up lo

__device__ __forceinline__ void split_bf16(float v, bf16& hi, bf16& lo) {
    hi = __float2bfloat16(v);
    lo = __float2bfloat16(v - __bfloat162float(hi));
}

// ---------------- embedding + positional ------------------------------------
__global__ void embed_kernel(const int* __restrict__ ids,
                             const float* __restrict__ et,
                             const float* __restrict__ es,
                             const float* __restrict__ pe,
                             float* __restrict__ x) {
    int t  = blockIdx.x;
    int id = ids[t];
    int s  = t % Sm;
    for (int d = threadIdx.x; d < Dm; d += blockDim.x) {
        long wi = (long)id * Dm + d;
        x[(long)t * Dm + d] = et[wi] * es[wi >> 7] + pe[s * Dm + d];
    }
}

// ---------------- RMSNorm -> hi/lo bf16 --------------------------------------
__global__ void rms_kernel(const float* __restrict__ X,
                           const float* __restrict__ w,
                           bf16* __restrict__ Yh, bf16* __restrict__ Yl) {
    int t = blockIdx.x, tid = threadIdx.x;
    __shared__ float red[256];
    float s = 0.f;
    for (int d = tid; d < Dm; d += 256) {
        float v = X[(long)t * Dm + d];
        s += v * v;
    }
    red[tid] = s; __syncthreads();
    for (int o = 128; o > 0; o >>= 1) {
        if (tid < o) red[tid] += red[tid + o];
        __syncthreads();
    }
    float r = rsqrtf(red[0] / Dm + 1e-6f);
    for (int d = tid; d < Dm; d += 256) {
        float v = X[(long)t * Dm + d] * r * w[d];
        bf16 hi, lo; split_bf16(v, hi, lo);
        Yh[(long)t * Dm + d] = hi;
        Yl[(long)t * Dm + d] = lo;
    }
}

// ---------------- tensor-core GEMM core with exact group dequant -------------
// Y[t,r] = (res? res[t,r]:0) + sum_g Sc[r*(IN/128)+g] * sum_{c in g} x[t,c]*W[r,c]
// Block tile 128x64, BK=64, 256 threads (8 warps, 32x32 warp tiles).
__device__ __forceinline__ void gemm_core(const bf16* __restrict__ Xh,
                                          const bf16* __restrict__ Xl,
                                          const float* __restrict__ W,
                                          const float* __restrict__ Sc,
                                          const float* __restrict__ res,
                                          float* __restrict__ Y,
                                          int R, int IN, int bm, int bn) {
    __shared__ bf16 sAh[128][72];
    __shared__ bf16 sAl[128][72];
    __shared__ bf16 sB [64][72];

    const int tid  = threadIdx.x;
    const int warp = tid >> 5, lane = tid & 31;
    const int warpM = warp & 3, warpN = warp >> 2;
    const int groups = IN >> 7;

    const int lr = lane >> 2;          // 0..7
    const int lc = (lane & 3) << 1;    // 0,2,4,6

    float master[2][4][4];
    float temp  [2][4][4];
    #pragma unroll
    for (int a = 0; a < 2; a++)
        #pragma unroll
        for (int b = 0; b < 4; b++)
            #pragma unroll
            for (int c = 0; c < 4; c++) { master[a][b][c] = 0.f; temp[a][b][c] = 0.f; }

    for (int k0 = 0; k0 < IN; k0 += 64) {
        {
            int row = tid >> 3;          // 0..31
            int c8  = (tid & 7) << 3;    // 0..56
            #pragma unroll
            for (int p = 0; p < 4; p++) {
                int m = row + p * 32;
                long gi = (long)(bm + m) * IN + k0 + c8;
                *(uint4*)&sAh[m][c8] = *(const uint4*)&Xh[gi];
                *(uint4*)&sAl[m][c8] = *(const uint4*)&Xl[gi];
            }
        }
        {
            int row = tid >> 4;          // 0..15
            int c4  = (tid & 15) << 2;   // 0..60
            #pragma unroll
            for (int p = 0; p < 4; p++) {
                int n = row + p * 16;
                float4 v = *(const float4*)&W[(long)(bn + n) * IN + k0 + c4];
                sB[n][c4 + 0] = __float2bfloat16(v.x);
                sB[n][c4 + 1] = __float2bfloat16(v.y);
                sB[n][c4 + 2] = __float2bfloat16(v.z);
                sB[n][c4 + 3] = __float2bfloat16(v.w);
            }
        }
        __syncthreads();

        #pragma unroll
        for (int ks = 0; ks < 4; ks++) {
            const int kb = ks * 16;
            uint32_t ah[2][4], al[2][4], bb[4][2];
            #pragma unroll
            for (int mt = 0; mt < 2; mt++) {
                int m0 = warpM * 32 + mt * 16;
                ah[mt][0] = *(const uint32_t*)&sAh[m0 + lr    ][kb + lc    ];
                ah[mt][1] = *(const uint32_t*)&sAh[m0 + lr + 8][kb + lc    ];
                ah[mt][2] = *(const uint32_t*)&sAh[m0 + lr    ][kb + lc + 8];
                ah[mt][3] = *(const uint32_t*)&sAh[m0 + lr + 8][kb + lc + 8];
                al[mt][0] = *(const uint32_t*)&sAl[m0 + lr    ][kb + lc    ];
                al[mt][1] = *(const uint32_t*)&sAl[m0 + lr + 8][kb + lc    ];
                al[mt][2] = *(const uint32_t*)&sAl[m0 + lr    ][kb + lc + 8];
                al[mt][3] = *(const uint32_t*)&sAl[m0 + lr + 8][kb + lc + 8];
            }
            #pragma unroll
            for (int nt = 0; nt < 4; nt++) {
                int n0 = warpN * 32 + nt * 8;
                bb[nt][0] = *(const uint32_t*)&sB[n0 + lr][kb + lc    ];
                bb[nt][1] = *(const uint32_t*)&sB[n0 + lr][kb + lc + 8];
            }
            #pragma unroll
            for (int mt = 0; mt < 2; mt++)
                #pragma unroll
                for (int nt = 0; nt < 4; nt++) {
                    float* d = temp[mt][nt];
                    asm volatile(
                        "mma.sync.aligned.m16n8k16.row.col.f32.bf16.bf16.f32 "
                        "{%0,%1,%2,%3}, {%4,%5,%6,%7}, {%8,%9}, {%0,%1,%2,%3};"
                        : "+f"(d[0]), "+f"(d[1]), "+f"(d[2]), "+f"(d[3])
                        : "r"(ah[mt][0]), "r"(ah[mt][1]), "r"(ah[mt][2]), "r"(ah[mt][3]),
                          "r"(bb[nt][0]), "r"(bb[nt][1]));
                    asm volatile(
                        "mma.sync.aligned.m16n8k16.row.col.f32.bf16.bf16.f32 "
                        "{%0,%1,%2,%3}, {%4,%5,%6,%7}, {%8,%9}, {%0,%1,%2,%3};"
                        : "+f"(d[0]), "+f"(d[1]), "+f"(d[2]), "+f"(d[3])
                        : "r"(al[mt][0]), "r"(al[mt][1]), "r"(al[mt][2]), "r"(al[mt][3]),
                          "r"(bb[nt][0]), "r"(bb[nt][1]));
                }
        }
        __syncthreads();

        if (((k0 + 64) & 127) == 0) {
            int g = k0 >> 7;
            #pragma unroll
            for (int nt = 0; nt < 4; nt++) {
                int r0 = bn + warpN * 32 + nt * 8 + lc;
                float s0 = __ldg(&Sc[(long)r0 * groups + g]);
                float s1 = __ldg(&Sc[(long)(r0 + 1) * groups + g]);
                #pragma unroll
                for (int mt = 0; mt < 2; mt++) {
                    master[mt][nt][0] += s0 * temp[mt][nt][0];
                    master[mt][nt][1] += s1 * temp[mt][nt][1];
                    master[mt][nt][2] += s0 * temp[mt][nt][2];
                    master[mt][nt][3] += s1 * temp[mt][nt][3];
                    temp[mt][nt][0] = 0.f; temp[mt][nt][1] = 0.f;
                    temp[mt][nt][2] = 0.f; temp[mt][nt][3] = 0.f;
                }
            }
        }
    }

    #pragma unroll
    for (int mt = 0; mt < 2; mt++) {
        int m0 = bm + warpM * 32 + mt * 16 + lr;
        #pragma unroll
        for (int nt = 0; nt < 4; nt++) {
            int r0 = bn + warpN * 32 + nt * 8 + lc;
            float2 v0 = make_float2(master[mt][nt][0], master[mt][nt][1]);
            float2 v1 = make_float2(master[mt][nt][2], master[mt][nt][3]);
            if (res) {
                float2 p0 = *(const float2*)&res[(long)m0 * R + r0];
                float2 p1 = *(const float2*)&res[(long)(m0 + 8) * R + r0];
                v0.x += p0.x; v0.y += p0.y;
                v1.x += p1.x; v1.y += p1.y;
            }
            *(float2*)&Y[(long)m0 * R + r0]       = v0;
            *(float2*)&Y[(long)(m0 + 8) * R + r0] = v1;
        }
    }
}

__global__ void gemm_mma_kernel(const bf16* __restrict__ Xh,
                                const bf16* __restrict__ Xl,
                                const float* __restrict__ W,
                                const float* __restrict__ Sc,
                                const float* __restrict__ res,
                                float* __restrict__ Y,
                                int R, int IN) {
    gemm_core(Xh, Xl, W, Sc, res, Y, R, IN, blockIdx.y * 128, blockIdx.x * 64);
}

// batched variant: z selects among up to 3 (W, Sc, Y) triples (no residual)
struct GB3 {
    const float *w0, *w1, *w2;
    const float *s0, *s1, *s2;
    float *y0, *y1, *y2;
};
__global__ void gemm_mma_batch(const bf16* __restrict__ Xh,
                               const bf16* __restrict__ Xl,
                               GB3 gb, int R, int IN) {
    int z = blockIdx.z;
    const float* W  = (z == 0) ? gb.w0 : (z == 1) ? gb.w1 : gb.w2;
    const float* Sc = (z == 0) ? gb.s0 : (z == 1) ? gb.s1 : gb.s2;
    float*       Y  = (z == 0) ? gb.y0 : (z == 1) ? gb.y1 : gb.y2;
    gemm_core(Xh, Xl, W, Sc, nullptr, Y, R, IN, blockIdx.y * 128, blockIdx.x * 64);
}

// ---------------- flash attention (fp32, 64-query tiles) ---------------------
// grid (S/64, H, B), 128 threads (4 warps x 16 rows). Online softmax.
// smem: sQ,sK,sV,sP each [64][65] fp32 -> 66560 B dynamic.
__global__ void attn_flash_kernel(const float* __restrict__ Q,
                                  const float* __restrict__ K,
                                  const float* __restrict__ V,
                                  const bf16* __restrict__ Hh,
                                  const bf16* __restrict__ Hl,
                                  const float* __restrict__ alpha,
                                  int layer,
                                  bf16* __restrict__ Oh, bf16* __restrict__ Ol) {
    extern __shared__ float sm[];
    float* sQ = sm;                  // [64][65]
    float* sK = sm + 64 * 65;        // [64][65]
    float* sV = sm + 2 * 64 * 65;    // [64][65]
    float* sP = sm + 3 * 64 * 65;    // [64][65]

    const int qt = blockIdx.x, h = blockIdx.y, b = blockIdx.z;
    const int tid = threadIdx.x, w = tid >> 5, ln = tid & 31;
    const int ry = ln >> 3, cx = ln & 7;     // 4x8 lane grid
    const int row0 = w * 16 + ry * 4;        // this lane's 4 rows (tile-local)
    const long tok0 = (long)b * Sm + qt * 64;
    const int hoff = h * 64;

    // load Q tile (64 rows x 64 dims)
    for (int i = tid; i < 64 * 16; i += 128) {
        int r = i >> 4, c4 = (i & 15) << 2;
        float4 v4 = *(const float4*)&Q[(tok0 + r) * Dm + hoff + c4];
        sQ[r * 65 + c4 + 0] = v4.x; sQ[r * 65 + c4 + 1] = v4.y;
        sQ[r * 65 + c4 + 2] = v4.z; sQ[r * 65 + c4 + 3] = v4.w;
    }

    float m[4], l[4], acc[4][8];
    #pragma unroll
    for (int r = 0; r < 4; r++) {
        m[r] = -1e30f; l[r] = 0.f;
        #pragma unroll
        for (int d = 0; d < 8; d++) acc[r][d] = 0.f;
    }

    const int nkt = qt + 1;
    for (int kt = 0; kt < nkt; kt++) {
        __syncthreads();
        long kbase = (long)b * Sm + kt * 64;
        for (int i = tid; i < 64 * 16; i += 128) {
            int r = i >> 4, c4 = (i & 15) << 2;
            float4 k4 = *(const float4*)&K[(kbase + r) * Dm + hoff + c4];
            sK[r * 65 + c4 + 0] = k4.x; sK[r * 65 + c4 + 1] = k4.y;
            sK[r * 65 + c4 + 2] = k4.z; sK[r * 65 + c4 + 3] = k4.w;
            float4 v4 = *(const float4*)&V[(kbase + r) * Dm + hoff + c4];
            sV[r * 65 + c4 + 0] = v4.x; sV[r * 65 + c4 + 1] = v4.y;
            sV[r * 65 + c4 + 2] = v4.z; sV[r * 65 + c4 + 3] = v4.w;
        }
        __syncthreads();

        // ---- QK^T: scores s[4 rows][8 cols], cols = cx*8..+7
        float s[4][8];
        #pragma unroll
        for (int r = 0; r < 4; r++)
            #pragma unroll
            for (int c = 0; c < 8; c++) s[r][c] = 0.f;
        for (int d = 0; d < 64; d++) {
            float qv[4], kv[8];
            #pragma unroll
            for (int r = 0; r < 4; r++) qv[r] = sQ[(row0 + r) * 65 + d];
            #pragma unroll
            for (int c = 0; c < 8; c++) kv[c] = sK[(cx * 8 + c) * 65 + d];
            #pragma unroll
            for (int r = 0; r < 4; r++)
                #pragma unroll
                for (int c = 0; c < 8; c++)
                    s[r][c] = fmaf(qv[r], kv[c], s[r][c]);
        }
        const bool diag = (kt == qt);
        #pragma unroll
        for (int r = 0; r < 4; r++)
            #pragma unroll
            for (int c = 0; c < 8; c++) {
                s[r][c] *= 0.125f;
                if (diag && (cx * 8 + c > row0 + r)) s[r][c] = -1e30f;
            }

        // ---- online softmax (reduce over the 8 lanes sharing ry)
        float fac[4];
        #pragma unroll
        for (int r = 0; r < 4; r++) {
            float mn = s[r][0];
            #pragma unroll
            for (int c = 1; c < 8; c++) mn = fmaxf(mn, s[r][c]);
            #pragma unroll
            for (int o = 1; o < 8; o <<= 1)
                mn = fmaxf(mn, __shfl_xor_sync(0xffffffffu, mn, o));
            mn = fmaxf(mn, m[r]);
            fac[r] = expf(m[r] - mn);
            m[r] = mn;
            float ls = 0.f;
            #pragma unroll
            for (int c = 0; c < 8; c++) {
                float p = expf(s[r][c] - mn);
                sP[(row0 + r) * 65 + cx * 8 + c] = p;
                ls += p;
            }
            #pragma unroll
            for (int o = 1; o < 8; o <<= 1)
                ls += __shfl_xor_sync(0xffffffffu, ls, o);
            l[r] = l[r] * fac[r] + ls;
            #pragma unroll
            for (int d = 0; d < 8; d++) acc[r][d] *= fac[r];
        }
        __syncwarp();

        // ---- PV: lane (ry, dx=cx) accumulates dims cx*8..+7 for its 4 rows
        for (int j = 0; j < 64; j++) {
            float pv[4], vv[8];
            #pragma unroll
            for (int r = 0; r < 4; r++) pv[r] = sP[(row0 + r) * 65 + j];
            #pragma unroll
            for (int d = 0; d < 8; d++) vv[d] = sV[j * 65 + cx * 8 + d];
            #pragma unroll
            for (int r = 0; r < 4; r++)
                #pragma unroll
                for (int d = 0; d < 8; d++)
                    acc[r][d] = fmaf(pv[r], vv[d], acc[r][d]);
        }
        __syncwarp();
    }

    // ---- epilogue: /l, + alpha*h, split to bf16 hi/lo
    float a = alpha[layer * Hm + h];
    #pragma unroll
    for (int r = 0; r < 4; r++) {
        float inv = 1.f / l[r];
        long t = tok0 + row0 + r;
        #pragma unroll
        for (int d = 0; d < 8; d++) {
            long oi = t * Dm + hoff + cx * 8 + d;
            float hn = __bfloat162float(Hh[oi]) + __bfloat162float(Hl[oi]);
            float v = acc[r][d] * inv + a * hn;
            bf16 hi, lo; split_bf16(v, hi, lo);
            Oh[oi] = hi; Ol[oi] = lo;
        }
    }
}

// ---------------- SiLU(gate) * up -> hi/lo bf16 -------------------------------
__global__ void silu_mul_kernel(const float* __restrict__ g,
                                const float* __restrict__ u,
                                bf16* __restrict__ Yh, bf16* __restrict__ Yl,
                                long n) {
    long i = (long)blockIdx.x * blockDim.x + threadIdx.x;
    if (i < n) {
        float x = g[i];
        float v = (x / (1.f + expf(-x))) * u[i];
        bf16 hi, lo; split_bf16(v, hi, lo);
        Yh[i] = hi; Yl[i] = lo;
    }
}

// =============================================================================
extern "C" void kernel_launch(void* const* d_in, const int* in_sizes, int n_in,
                              void* d_out, int out_size) {
    const int*   ids    = (const int*)  d_in[0];
    const float* emb_t  = (const float*)d_in[1];
    const float* emb_s  = (const float*)d_in[2];
    const float* pos    = (const float*)d_in[3];
    const float* q_t    = (const float*)d_in[4];
    const float* q_s    = (const float*)d_in[5];
    const float* k_t    = (const float*)d_in[6];
    const float* k_s    = (const float*)d_in[7];
    const float* v_t    = (const float*)d_in[8];
    const float* v_s    = (const float*)d_in[9];
    const float* o_t    = (const float*)d_in[10];
    const float* o_s    = (const float*)d_in[11];
    const float* gt     = (const float*)d_in[12];
    const float* gs     = (const float*)d_in[13];
    const float* ut     = (const float*)d_in[14];
    const float* us     = (const float*)d_in[15];
    const float* dt     = (const float*)d_in[16];
    const float* ds     = (const float*)d_in[17];
    const float* alpha  = (const float*)d_in[18];
    const float* na_w   = (const float*)d_in[19];
    const float* nm_w   = (const float*)d_in[20];
    const float* nf_w   = (const float*)d_in[21];
    const float* head_t = (const float*)d_in[22];
    const float* head_s = (const float*)d_in[23];

    float *x, *q, *k, *v, *gate, *up;
    bf16 *hh, *hl, *ah, *al, *gh, *gl;
    cudaGetSymbolAddress((void**)&x,    g_x);
    cudaGetSymbolAddress((void**)&hh,   g_hh);
    cudaGetSymbolAddress((void**)&hl,   g_hl);
    cudaGetSymbolAddress((void**)&q,    g_q);
    cudaGetSymbolAddress((void**)&k,    g_k);
    cudaGetSymbolAddress((void**)&v,    g_v);
    cudaGetSymbolAddress((void**)&ah,   g_ah);
    cudaGetSymbolAddress((void**)&al,   g_al);
    cudaGetSymbolAddress((void**)&gate, g_gate);
    cudaGetSymbolAddress((void**)&up,   g_up);
    cudaGetSymbolAddress((void**)&gh,   g_gh);
    cudaGetSymbolAddress((void**)&gl,   g_gl);

    const long sQsz = (long)Dm * Dm / 128;
    const long sFsz = (long)Dm * FFm / 128;
    const int ATTN_SMEM = 4 * 64 * 65 * sizeof(float);  // 66560
    cudaFuncSetAttribute(attn_flash_kernel,
                         cudaFuncAttributeMaxDynamicSharedMemorySize, ATTN_SMEM);

    embed_kernel<<<Tn, 256>>>(ids, emb_t, emb_s, pos, x);

    dim3 gD(Dm / 64,  Tn / 128);        // 16 x 16
    dim3 gQKV(Dm / 64,  Tn / 128, 3);   // 768 blocks
    dim3 gGU(FFm / 64, Tn / 128, 2);    // 2048 blocks
    dim3 gV(Vv / 64,  Tn / 128);        // 8000 blocks
    dim3 ga(Sm / 64, Hm, Bm);           // 512 blocks

    for (int l = 0; l < Lm; l++) {
        rms_kernel<<<Tn, 256>>>(x, na_w + l * Dm, hh, hl);

        GB3 qkv;
        qkv.w0 = q_t + (long)l * Dm * Dm; qkv.s0 = q_s + l * sQsz; qkv.y0 = q;
        qkv.w1 = k_t + (long)l * Dm * Dm; qkv.s1 = k_s + l * sQsz; qkv.y1 = k;
        qkv.w2 = v_t + (long)l * Dm * Dm; qkv.s2 = v_s + l * sQsz; qkv.y2 = v;
        gemm_mma_batch<<<gQKV, 256>>>(hh, hl, qkv, Dm, Dm);

        attn_flash_kernel<<<ga, 128, ATTN_SMEM>>>(q, k, v, hh, hl, alpha, l, ah, al);

        // x = x + att @ O^T
        gemm_mma_kernel<<<gD, 256>>>(ah, al, o_t + (long)l * Dm * Dm,
                                     o_s + l * sQsz, x, x, Dm, Dm);

        rms_kernel<<<Tn, 256>>>(x, nm_w + l * Dm, hh, hl);

        GB3 gu;
        gu.w0 = gt + (long)l * FFm * Dm; gu.s0 = gs + l * sFsz; gu.y0 = gate;
        gu.w1 = ut + (long)l * FFm * Dm; gu.s1 = us + l * sFsz; gu.y1 = up;
        gu.w2 = gu.w1; gu.s2 = gu.s1; gu.y2 = up;  // unused (z<2)
        gemm_mma_batch<<<gGU, 256>>>(hh, hl, gu, FFm, Dm);

        long n = (long)Tn * FFm;
        silu_mul_kernel<<<(unsigned)((n + 255) / 256), 256>>>(gate, up, gh, gl, n);

        // x = x + (silu(gate)*up) @ D^T
        gemm_mma_kernel<<<gD, 256>>>(gh, gl, dt + (long)l * Dm * FFm,
                                     ds + l * sFsz, x, x, Dm, FFm);
    }

    rms_kernel<<<Tn, 256>>>(x, nf_w, hh, hl);
    gemm_mma_kernel<<<gV, 256>>>(hh, hl, head_t, head_s, nullptr,
                                 (float*)d_out, Vv, Dm);
}

// round 4
// speedup vs baseline: 8.4933x; 1.0681x over previous
#include <cuda_runtime.h>
#include <cuda_bf16.h>
#include <math.h>
#include <stdint.h>

#define Tn  2048   // B*S tokens
#define Dm  1024
#define FFm 4096
#define Vv  32000
#define Bm  2
#define Sm  1024
#define Hm  16
#define Lm  6

typedef __nv_bfloat16 bf16;

// ---------------- scratch (static device globals; no allocation) ------------
__device__ float g_x  [Tn * Dm];
__device__ bf16  g_hh [Tn * Dm];
__device__ bf16  g_hl [Tn * Dm];
__device__ float g_q  [Tn * Dm];
__device__ float g_k  [Tn * Dm];
__device__ float g_v  [Tn * Dm];
__device__ bf16  g_ah [Tn * Dm];
__device__ bf16  g_al [Tn * Dm];
__device__ float g_gate[(long)Tn * FFm];
__device__ float g_up  [(long)Tn * FFm];
__device__ bf16  g_gh [(long)Tn * FFm];
__device__ bf16  g_gl [(long)Tn * FFm];

// bf16 weight caches (converted once per launch)
__device__ bf16 g_wq[(long)Lm * Dm * Dm];
__device__ bf16 g_wk[(long)Lm * Dm * Dm];
__device__ bf16 g_wv[(long)Lm * Dm * Dm];
__device__ bf16 g_wo[(long)Lm * Dm * Dm];
__device__ bf16 g_wg[(long)Lm * FFm * Dm];
__device__ bf16 g_wu[(long)Lm * FFm * Dm];
__device__ bf16 g_wd[(long)Lm * FFm * Dm];
__device__ bf16 g_wh[(long)Vv * Dm];

__device__ __forceinline__ void split_bf16(float v, bf16& hi, bf16& lo) {
    hi = __float2bfloat16(v);
    lo = __float2bfloat16(v - __bfloat162float(hi));
}

__device__ __forceinline__ void cp_async16(void* dst, const void* src) {
    uint32_t d = (uint32_t)__cvta_generic_to_shared(dst);
    asm volatile("cp.async.cg.shared.global [%0], [%1], 16;" :: "r"(d), "l"(src));
}
__device__ __forceinline__ void cp_commit() {
    asm volatile("cp.async.commit_group;");
}

// ---------------- weight fp32 -> bf16 ---------------------------------------
__global__ void w2b_kernel(const float* __restrict__ s, bf16* __restrict__ d,
                           long n) {
    long i = ((long)blockIdx.x * blockDim.x + threadIdx.x) * 4;
    if (i < n) {
        float4 v = *(const float4*)&s[i];
        *(__nv_bfloat162*)&d[i]     = __floats2bfloat162_rn(v.x, v.y);
        *(__nv_bfloat162*)&d[i + 2] = __floats2bfloat162_rn(v.z, v.w);
    }
}

// ---------------- embedding + positional ------------------------------------
__global__ void embed_kernel(const int* __restrict__ ids,
                             const float* __restrict__ et,
                             const float* __restrict__ es,
                             const float* __restrict__ pe,
                             float* __restrict__ x) {
    int t  = blockIdx.x;
    int id = ids[t];
    int s  = t % Sm;
    for (int d = threadIdx.x; d < Dm; d += blockDim.x) {
        long wi = (long)id * Dm + d;
        x[(long)t * Dm + d] = et[wi] * es[wi >> 7] + pe[s * Dm + d];
    }
}

// ---------------- RMSNorm -> hi/lo bf16 --------------------------------------
__global__ void rms_kernel(const float* __restrict__ X,
                           const float* __restrict__ w,
                           bf16* __restrict__ Yh, bf16* __restrict__ Yl) {
    int t = blockIdx.x, tid = threadIdx.x;
    __shared__ float red[256];
    float s = 0.f;
    for (int d = tid; d < Dm; d += 256) {
        float v = X[(long)t * Dm + d];
        s += v * v;
    }
    red[tid] = s; __syncthreads();
    for (int o = 128; o > 0; o >>= 1) {
        if (tid < o) red[tid] += red[tid + o];
        __syncthreads();
    }
    float r = rsqrtf(red[0] / Dm + 1e-6f);
    for (int d = tid; d < Dm; d += 256) {
        float v = X[(long)t * Dm + d] * r * w[d];
        bf16 hi, lo; split_bf16(v, hi, lo);
        Yh[(long)t * Dm + d] = hi;
        Yl[(long)t * Dm + d] = lo;
    }
}

// ---------------- double-buffered tensor-core GEMM ---------------------------
// Y[t,r] = (res? res[t,r]:0) + sum_g Sc[r*(IN/128)+g] * sum_{c in g} x[t,c]*W[r,c]
// Block 128x64, BK=64, 2-stage cp.async pipeline, 256 threads.
#define SAS 72
__device__ __forceinline__ void gemm_core(const bf16* __restrict__ Xh,
                                          const bf16* __restrict__ Xl,
                                          const bf16* __restrict__ W,
                                          const float* __restrict__ Sc,
                                          const float* __restrict__ res,
                                          float* __restrict__ Y,
                                          int R, int IN, int bm, int bn) {
    extern __shared__ bf16 smp[];
    bf16* sAh = smp;                       // [2][128][SAS]
    bf16* sAl = smp + 2 * 128 * SAS;       // [2][128][SAS]
    bf16* sB  = smp + 4 * 128 * SAS;       // [2][64][SAS]

    const int tid  = threadIdx.x;
    const int warp = tid >> 5, lane = tid & 31;
    const int warpM = warp & 3, warpN = warp >> 2;
    const int groups = IN >> 7;
    const int lr = lane >> 2;
    const int lc = (lane & 3) << 1;

    float master[2][4][4];
    float temp  [2][4][4];
    #pragma unroll
    for (int a = 0; a < 2; a++)
        #pragma unroll
        for (int b = 0; b < 4; b++)
            #pragma unroll
            for (int c = 0; c < 4; c++) { master[a][b][c] = 0.f; temp[a][b][c] = 0.f; }

    const int nIter = IN >> 6;

    // stage loader
    auto load_stage = [&](int st, int k0) {
        bf16* ah = sAh + st * 128 * SAS;
        bf16* al = sAl + st * 128 * SAS;
        bf16* bw = sB  + st * 64 * SAS;
        #pragma unroll
        for (int p = 0; p < 4; p++) {
            int idx = tid + p * 256;
            int m = idx >> 3, c8 = (idx & 7) << 3;
            long gi = (long)(bm + m) * IN + k0 + c8;
            cp_async16(ah + m * SAS + c8, Xh + gi);
            cp_async16(al + m * SAS + c8, Xl + gi);
        }
        #pragma unroll
        for (int p = 0; p < 2; p++) {
            int idx = tid + p * 256;
            int n = idx >> 3, c8 = (idx & 7) << 3;
            cp_async16(bw + n * SAS + c8, W + (long)(bn + n) * IN + k0 + c8);
        }
    };

    load_stage(0, 0);
    cp_commit();

    for (int it = 0; it < nIter; it++) {
        if (it + 1 < nIter) {
            load_stage((it + 1) & 1, (it + 1) << 6);
            cp_commit();
            asm volatile("cp.async.wait_group 1;");
        } else {
            asm volatile("cp.async.wait_group 0;");
        }
        __syncthreads();

        const int st = it & 1;
        const bf16* ah = sAh + st * 128 * SAS;
        const bf16* al = sAl + st * 128 * SAS;
        const bf16* bw = sB  + st * 64 * SAS;

        #pragma unroll
        for (int ks = 0; ks < 4; ks++) {
            const int kb = ks * 16;
            uint32_t fah[2][4], fal[2][4], fb[4][2];
            #pragma unroll
            for (int mt = 0; mt < 2; mt++) {
                int m0 = warpM * 32 + mt * 16;
                fah[mt][0] = *(const uint32_t*)&ah[(m0 + lr    ) * SAS + kb + lc    ];
                fah[mt][1] = *(const uint32_t*)&ah[(m0 + lr + 8) * SAS + kb + lc    ];
                fah[mt][2] = *(const uint32_t*)&ah[(m0 + lr    ) * SAS + kb + lc + 8];
                fah[mt][3] = *(const uint32_t*)&ah[(m0 + lr + 8) * SAS + kb + lc + 8];
                fal[mt][0] = *(const uint32_t*)&al[(m0 + lr    ) * SAS + kb + lc    ];
                fal[mt][1] = *(const uint32_t*)&al[(m0 + lr + 8) * SAS + kb + lc    ];
                fal[mt][2] = *(const uint32_t*)&al[(m0 + lr    ) * SAS + kb + lc + 8];
                fal[mt][3] = *(const uint32_t*)&al[(m0 + lr + 8) * SAS + kb + lc + 8];
            }
            #pragma unroll
            for (int nt = 0; nt < 4; nt++) {
                int n0 = warpN * 32 + nt * 8;
                fb[nt][0] = *(const uint32_t*)&bw[(n0 + lr) * SAS + kb + lc    ];
                fb[nt][1] = *(const uint32_t*)&bw[(n0 + lr) * SAS + kb + lc + 8];
            }
            #pragma unroll
            for (int mt = 0; mt < 2; mt++)
                #pragma unroll
                for (int nt = 0; nt < 4; nt++) {
                    float* d = temp[mt][nt];
                    asm volatile(
                        "mma.sync.aligned.m16n8k16.row.col.f32.bf16.bf16.f32 "
                        "{%0,%1,%2,%3}, {%4,%5,%6,%7}, {%8,%9}, {%0,%1,%2,%3};"
                        : "+f"(d[0]), "+f"(d[1]), "+f"(d[2]), "+f"(d[3])
                        : "r"(fah[mt][0]), "r"(fah[mt][1]), "r"(fah[mt][2]), "r"(fah[mt][3]),
                          "r"(fb[nt][0]), "r"(fb[nt][1]));
                    asm volatile(
                        "mma.sync.aligned.m16n8k16.row.col.f32.bf16.bf16.f32 "
                        "{%0,%1,%2,%3}, {%4,%5,%6,%7}, {%8,%9}, {%0,%1,%2,%3};"
                        : "+f"(d[0]), "+f"(d[1]), "+f"(d[2]), "+f"(d[3])
                        : "r"(fal[mt][0]), "r"(fal[mt][1]), "r"(fal[mt][2]), "r"(fal[mt][3]),
                          "r"(fb[nt][0]), "r"(fb[nt][1]));
                }
        }

        if (it & 1) {  // 128-K group boundary: fold temp into master
            int g = it >> 1;
            #pragma unroll
            for (int nt = 0; nt < 4; nt++) {
                int r0 = bn + warpN * 32 + nt * 8 + lc;
                float s0 = __ldg(&Sc[(long)r0 * groups + g]);
                float s1 = __ldg(&Sc[(long)(r0 + 1) * groups + g]);
                #pragma unroll
                for (int mt = 0; mt < 2; mt++) {
                    master[mt][nt][0] += s0 * temp[mt][nt][0];
                    master[mt][nt][1] += s1 * temp[mt][nt][1];
                    master[mt][nt][2] += s0 * temp[mt][nt][2];
                    master[mt][nt][3] += s1 * temp[mt][nt][3];
                    temp[mt][nt][0] = 0.f; temp[mt][nt][1] = 0.f;
                    temp[mt][nt][2] = 0.f; temp[mt][nt][3] = 0.f;
                }
            }
        }
        __syncthreads();
    }

    #pragma unroll
    for (int mt = 0; mt < 2; mt++) {
        int m0 = bm + warpM * 32 + mt * 16 + lr;
        #pragma unroll
        for (int nt = 0; nt < 4; nt++) {
            int r0 = bn + warpN * 32 + nt * 8 + lc;
            float2 v0 = make_float2(master[mt][nt][0], master[mt][nt][1]);
            float2 v1 = make_float2(master[mt][nt][2], master[mt][nt][3]);
            if (res) {
                float2 p0 = *(const float2*)&res[(long)m0 * R + r0];
                float2 p1 = *(const float2*)&res[(long)(m0 + 8) * R + r0];
                v0.x += p0.x; v0.y += p0.y;
                v1.x += p1.x; v1.y += p1.y;
            }
            *(float2*)&Y[(long)m0 * R + r0]       = v0;
            *(float2*)&Y[(long)(m0 + 8) * R + r0] = v1;
        }
    }
}

__global__ void __launch_bounds__(256)
gemm_mma_kernel(const bf16* __restrict__ Xh, const bf16* __restrict__ Xl,
                const bf16* __restrict__ W, const float* __restrict__ Sc,
                const float* __restrict__ res, float* __restrict__ Y,
                int R, int IN) {
    gemm_core(Xh, Xl, W, Sc, res, Y, R, IN, blockIdx.y * 128, blockIdx.x * 64);
}

struct GB3 {
    const bf16 *w0, *w1, *w2;
    const float *s0, *s1, *s2;
    float *y0, *y1, *y2;
};
__global__ void __launch_bounds__(256)
gemm_mma_batch(const bf16* __restrict__ Xh, const bf16* __restrict__ Xl,
               GB3 gb, int R, int IN) {
    int z = blockIdx.z;
    const bf16*  W  = (z == 0) ? gb.w0 : (z == 1) ? gb.w1 : gb.w2;
    const float* Sc = (z == 0) ? gb.s0 : (z == 1) ? gb.s1 : gb.s2;
    float*       Y  = (z == 0) ? gb.y0 : (z == 1) ? gb.y1 : gb.y2;
    gemm_core(Xh, Xl, W, Sc, nullptr, Y, R, IN, blockIdx.y * 128, blockIdx.x * 64);
}

// ---------------- balanced flash attention ----------------------------------
// grid (S/128, H, B): block handles q-tiles {bx, 15-bx} -> 17 k-tiles each.
__global__ void __launch_bounds__(128)
attn_flash_kernel(const float* __restrict__ Q,
                  const float* __restrict__ K,
                  const float* __restrict__ V,
                  const bf16* __restrict__ Hh,
                  const bf16* __restrict__ Hl,
                  const float* __restrict__ alpha,
                  int layer,
                  bf16* __restrict__ Oh, bf16* __restrict__ Ol) {
    extern __shared__ float sm[];
    float* sQ = sm;
    float* sK = sm + 64 * 65;
    float* sV = sm + 2 * 64 * 65;
    float* sP = sm + 3 * 64 * 65;

    const int nQT = Sm / 64;
    const int h = blockIdx.y, b = blockIdx.z;
    const int tid = threadIdx.x, w = tid >> 5, ln = tid & 31;
    const int ry = ln >> 3, cx = ln & 7;
    const int row0 = w * 16 + ry * 4;
    const int hoff = h * 64;

    #pragma unroll
    for (int pass = 0; pass < 2; pass++) {
        const int qt = (pass == 0) ? blockIdx.x : (nQT - 1 - blockIdx.x);
        const long tok0 = (long)b * Sm + qt * 64;

        __syncthreads();
        for (int i = tid; i < 64 * 16; i += 128) {
            int r = i >> 4, c4 = (i & 15) << 2;
            float4 v4 = *(const float4*)&Q[(tok0 + r) * Dm + hoff + c4];
            sQ[r * 65 + c4 + 0] = v4.x; sQ[r * 65 + c4 + 1] = v4.y;
            sQ[r * 65 + c4 + 2] = v4.z; sQ[r * 65 + c4 + 3] = v4.w;
        }

        float m[4], l[4], acc[4][8];
        #pragma unroll
        for (int r = 0; r < 4; r++) {
            m[r] = -1e30f; l[r] = 0.f;
            #pragma unroll
            for (int d = 0; d < 8; d++) acc[r][d] = 0.f;
        }

        const int nkt = qt + 1;
        for (int kt = 0; kt < nkt; kt++) {
            __syncthreads();
            long kbase = (long)b * Sm + kt * 64;
            for (int i = tid; i < 64 * 16; i += 128) {
                int r = i >> 4, c4 = (i & 15) << 2;
                float4 k4 = *(const float4*)&K[(kbase + r) * Dm + hoff + c4];
                sK[r * 65 + c4 + 0] = k4.x; sK[r * 65 + c4 + 1] = k4.y;
                sK[r * 65 + c4 + 2] = k4.z; sK[r * 65 + c4 + 3] = k4.w;
                float4 v4 = *(const float4*)&V[(kbase + r) * Dm + hoff + c4];
                sV[r * 65 + c4 + 0] = v4.x; sV[r * 65 + c4 + 1] = v4.y;
                sV[r * 65 + c4 + 2] = v4.z; sV[r * 65 + c4 + 3] = v4.w;
            }
            __syncthreads();

            float s[4][8];
            #pragma unroll
            for (int r = 0; r < 4; r++)
                #pragma unroll
                for (int c = 0; c < 8; c++) s[r][c] = 0.f;
            for (int d = 0; d < 64; d++) {
                float qv[4], kv[8];
                #pragma unroll
                for (int r = 0; r < 4; r++) qv[r] = sQ[(row0 + r) * 65 + d];
                #pragma unroll
                for (int c = 0; c < 8; c++) kv[c] = sK[(cx * 8 + c) * 65 + d];
                #pragma unroll
                for (int r = 0; r < 4; r++)
                    #pragma unroll
                    for (int c = 0; c < 8; c++)
                        s[r][c] = fmaf(qv[r], kv[c], s[r][c]);
            }
            const bool diag = (kt == qt);
            #pragma unroll
            for (int r = 0; r < 4; r++)
                #pragma unroll
                for (int c = 0; c < 8; c++) {
                    s[r][c] *= 0.125f;
                    if (diag && (cx * 8 + c > row0 + r)) s[r][c] = -1e30f;
                }

            #pragma unroll
            for (int r = 0; r < 4; r++) {
                float mn = s[r][0];
                #pragma unroll
                for (int c = 1; c < 8; c++) mn = fmaxf(mn, s[r][c]);
                #pragma unroll
                for (int o = 1; o < 8; o <<= 1)
                    mn = fmaxf(mn, __shfl_xor_sync(0xffffffffu, mn, o));
                mn = fmaxf(mn, m[r]);
                float fac = expf(m[r] - mn);
                m[r] = mn;
                float ls = 0.f;
                #pragma unroll
                for (int c = 0; c < 8; c++) {
                    float p = expf(s[r][c] - mn);
                    sP[(row0 + r) * 65 + cx * 8 + c] = p;
                    ls += p;
                }
                #pragma unroll
                for (int o = 1; o < 8; o <<= 1)
                    ls += __shfl_xor_sync(0xffffffffu, ls, o);
                l[r] = l[r] * fac + ls;
                #pragma unroll
                for (int d = 0; d < 8; d++) acc[r][d] *= fac;
            }
            __syncwarp();

            for (int j = 0; j < 64; j++) {
                float pv[4], vv[8];
                #pragma unroll
                for (int r = 0; r < 4; r++) pv[r] = sP[(row0 + r) * 65 + j];
                #pragma unroll
                for (int d = 0; d < 8; d++) vv[d] = sV[j * 65 + cx * 8 + d];
                #pragma unroll
                for (int r = 0; r < 4; r++)
                    #pragma unroll
                    for (int d = 0; d < 8; d++)
                        acc[r][d] = fmaf(pv[r], vv[d], acc[r][d]);
            }
            __syncwarp();
        }

        float a = alpha[layer * Hm + h];
        #pragma unroll
        for (int r = 0; r < 4; r++) {
            float inv = 1.f / l[r];
            long t = tok0 + row0 + r;
            #pragma unroll
            for (int d = 0; d < 8; d++) {
                long oi = t * Dm + hoff + cx * 8 + d;
                float hn = __bfloat162float(Hh[oi]) + __bfloat162float(Hl[oi]);
                float v = acc[r][d] * inv + a * hn;
                bf16 hi, lo; split_bf16(v, hi, lo);
                Oh[oi] = hi; Ol[oi] = lo;
            }
        }
    }
}

// ---------------- SiLU(gate) * up -> hi/lo bf16 -------------------------------
__global__ void silu_mul_kernel(const float* __restrict__ g,
                                const float* __restrict__ u,
                                bf16* __restrict__ Yh, bf16* __restrict__ Yl,
                                long n) {
    long i = (long)blockIdx.x * blockDim.x + threadIdx.x;
    if (i < n) {
        float x = g[i];
        float v = (x / (1.f + expf(-x))) * u[i];
        bf16 hi, lo; split_bf16(v, hi, lo);
        Yh[i] = hi; Yl[i] = lo;
    }
}

// =============================================================================
extern "C" void kernel_launch(void* const* d_in, const int* in_sizes, int n_in,
                              void* d_out, int out_size) {
    const int*   ids    = (const int*)  d_in[0];
    const float* emb_t  = (const float*)d_in[1];
    const float* emb_s  = (const float*)d_in[2];
    const float* pos    = (const float*)d_in[3];
    const float* q_t    = (const float*)d_in[4];
    const float* q_s    = (const float*)d_in[5];
    const float* k_t    = (const float*)d_in[6];
    const float* k_s    = (const float*)d_in[7];
    const float* v_t    = (const float*)d_in[8];
    const float* v_s    = (const float*)d_in[9];
    const float* o_t    = (const float*)d_in[10];
    const float* o_s    = (const float*)d_in[11];
    const float* gt     = (const float*)d_in[12];
    const float* gs     = (const float*)d_in[13];
    const float* ut     = (const float*)d_in[14];
    const float* us     = (const float*)d_in[15];
    const float* dt     = (const float*)d_in[16];
    const float* ds     = (const float*)d_in[17];
    const float* alpha  = (const float*)d_in[18];
    const float* na_w   = (const float*)d_in[19];
    const float* nm_w   = (const float*)d_in[20];
    const float* nf_w   = (const float*)d_in[21];
    const float* head_t = (const float*)d_in[22];
    const float* head_s = (const float*)d_in[23];

    float *x, *q, *k, *v, *gate, *up;
    bf16 *hh, *hl, *ah, *al, *gh, *gl;
    bf16 *wq, *wk, *wv, *wo, *wg, *wu, *wd, *wh;
    cudaGetSymbolAddress((void**)&x,    g_x);
    cudaGetSymbolAddress((void**)&hh,   g_hh);
    cudaGetSymbolAddress((void**)&hl,   g_hl);
    cudaGetSymbolAddress((void**)&q,    g_q);
    cudaGetSymbolAddress((void**)&k,    g_k);
    cudaGetSymbolAddress((void**)&v,    g_v);
    cudaGetSymbolAddress((void**)&ah,   g_ah);
    cudaGetSymbolAddress((void**)&al,   g_al);
    cudaGetSymbolAddress((void**)&gate, g_gate);
    cudaGetSymbolAddress((void**)&up,   g_up);
    cudaGetSymbolAddress((void**)&gh,   g_gh);
    cudaGetSymbolAddress((void**)&gl,   g_gl);
    cudaGetSymbolAddress((void**)&wq,   g_wq);
    cudaGetSymbolAddress((void**)&wk,   g_wk);
    cudaGetSymbolAddress((void**)&wv,   g_wv);
    cudaGetSymbolAddress((void**)&wo,   g_wo);
    cudaGetSymbolAddress((void**)&wg,   g_wg);
    cudaGetSymbolAddress((void**)&wu,   g_wu);
    cudaGetSymbolAddress((void**)&wd,   g_wd);
    cudaGetSymbolAddress((void**)&wh,   g_wh);

    const long sQsz = (long)Dm * Dm / 128;
    const long sFsz = (long)Dm * FFm / 128;

    static bool attr_done = false;
    const int GEMM_SMEM = (4 * 128 * SAS + 2 * 64 * SAS) * (int)sizeof(bf16); // 92160
    const int ATTN_SMEM = 4 * 64 * 65 * (int)sizeof(float);                   // 66560
    if (!attr_done) {
        cudaFuncSetAttribute(gemm_mma_kernel,
                             cudaFuncAttributeMaxDynamicSharedMemorySize, GEMM_SMEM);
        cudaFuncSetAttribute(gemm_mma_batch,
                             cudaFuncAttributeMaxDynamicSharedMemorySize, GEMM_SMEM);
        cudaFuncSetAttribute(attn_flash_kernel,
                             cudaFuncAttributeMaxDynamicSharedMemorySize, ATTN_SMEM);
        attr_done = true;
    }

    // ---- weight conversion (once per launch, identical work every call) ----
    {
        long nD = (long)Lm * Dm * Dm;    // 6.29M
        long nF = (long)Lm * FFm * Dm;   // 25.2M
        long nH = (long)Vv * Dm;         // 32.77M
        int th = 256;
        w2b_kernel<<<(unsigned)((nD / 4 + th - 1) / th), th>>>(q_t, wq, nD);
        w2b_kernel<<<(unsigned)((nD / 4 + th - 1) / th), th>>>(k_t, wk, nD);
        w2b_kernel<<<(unsigned)((nD / 4 + th - 1) / th), th>>>(v_t, wv, nD);
        w2b_kernel<<<(unsigned)((nD / 4 + th - 1) / th), th>>>(o_t, wo, nD);
        w2b_kernel<<<(unsigned)((nF / 4 + th - 1) / th), th>>>(gt,  wg, nF);
        w2b_kernel<<<(unsigned)((nF / 4 + th - 1) / th), th>>>(ut,  wu, nF);
        w2b_kernel<<<(unsigned)((nF / 4 + th - 1) / th), th>>>(dt,  wd, nF);
        w2b_kernel<<<(unsigned)((nH / 4 + th - 1) / th), th>>>(head_t, wh, nH);
    }

    embed_kernel<<<Tn, 256>>>(ids, emb_t, emb_s, pos, x);

    dim3 gD(Dm / 64,  Tn / 128);
    dim3 gQKV(Dm / 64,  Tn / 128, 3);
    dim3 gGU(FFm / 64, Tn / 128, 2);
    dim3 gV(Vv / 64,  Tn / 128);
    dim3 ga(Sm / 128, Hm, Bm);   // 8 x 16 x 2 = 256 balanced blocks

    for (int l = 0; l < Lm; l++) {
        rms_kernel<<<Tn, 256>>>(x, na_w + l * Dm, hh, hl);

        GB3 qkv;
        qkv.w0 = wq + (long)l * Dm * Dm; qkv.s0 = q_s + l * sQsz; qkv.y0 = q;
        qkv.w1 = wk + (long)l * Dm * Dm; qkv.s1 = k_s + l * sQsz; qkv.y1 = k;
        qkv.w2 = wv + (long)l * Dm * Dm; qkv.s2 = v_s + l * sQsz; qkv.y2 = v;
        gemm_mma_batch<<<gQKV, 256, GEMM_SMEM>>>(hh, hl, qkv, Dm, Dm);

        attn_flash_kernel<<<ga, 128, ATTN_SMEM>>>(q, k, v, hh, hl, alpha, l, ah, al);

        gemm_mma_kernel<<<gD, 256, GEMM_SMEM>>>(ah, al, wo + (long)l * Dm * Dm,
                                                o_s + l * sQsz, x, x, Dm, Dm);

        rms_kernel<<<Tn, 256>>>(x, nm_w + l * Dm, hh, hl);

        GB3 gu;
        gu.w0 = wg + (long)l * FFm * Dm; gu.s0 = gs + l * sFsz; gu.y0 = gate;
        gu.w1 = wu + (long)l * FFm * Dm; gu.s1 = us + l * sFsz; gu.y1 = up;
        gu.w2 = gu.w1; gu.s2 = gu.s1; gu.y2 = up;
        gemm_mma_batch<<<gGU, 256, GEMM_SMEM>>>(hh, hl, gu, FFm, Dm);

        long n = (long)Tn * FFm;
        silu_mul_kernel<<<(unsigned)((n + 255) / 256), 256>>>(gate, up, gh, gl, n);

        gemm_mma_kernel<<<gD, 256, GEMM_SMEM>>>(gh, gl, wd + (long)l * Dm * FFm,
                                                ds + l * sFsz, x, x, Dm, FFm);
    }

    rms_kernel<<<Tn, 256>>>(x, nf_w, hh, hl);
    gemm_mma_kernel<<<gV, 256, GEMM_SMEM>>>(hh, hl, wh, head_s, nullptr,
                                            (float*)d_out, Vv, Dm);
}